// round 7
// baseline (speedup 1.0000x reference)
#include <cuda_runtime.h>

#define KS   13
#define RAD  6
#define TW   32
#define TH   2            // block covers 32x2 outputs; 128 threads, 2 per output
#define PW   (TW + 2*RAD) // 44
#define PH   (TH + 2*RAD) // 14
#define IMH  256
#define IMW  256
#define NC   4
#define NB   2
#define NT   128

__device__ __forceinline__ float fast_ex2(float x) {
    float r; asm("ex2.approx.ftz.f32 %0, %1;" : "=f"(r) : "f"(x)); return r;
}

__global__ __launch_bounds__(NT, 10)
void bilateral13_v7(const float* __restrict__ x, float* __restrict__ out) {
    __shared__ float4 tile[PH][PW];   // sc * (u01, v01, u23, v23) basis
    __shared__ float  s_T[KS * KS];   // K2 * ((iy-6)^2 + (ix-6)^2)

    const int tid = threadIdx.x;      // 0..127
    const int b   = blockIdx.z;
    const int tx0 = blockIdx.x * TW;
    const int ty0 = blockIdx.y * TH;

    const float K2 = (-0.5f / 9.0f) * 1.4426950408889634f;
    const float SC = 0.28311592f;     // sqrt(-K2)

    // ---- spatial table ----
    for (int e = tid; e < KS * KS; e += NT) {
        const int iy = e / KS - RAD;
        const int ix = e % KS - RAD;
        s_T[e] = K2 * (float)(iy * iy + ix * ix);
    }

    // ---- cooperative load: reflect pad, (u,v) basis change, pre-scale -----
    const float* xb = x + (size_t)b * NC * IMH * IMW;
    #pragma unroll
    for (int it = 0; it < (PH * PW + NT - 1) / NT; it++) {
        int i = tid + it * NT;
        if (i < PH * PW) {
            int py = i / PW, px = i % PW;
            int gy = ty0 + py - RAD;
            int gx = tx0 + px - RAD;
            gy = (gy < 0) ? -gy : ((gy >= IMH) ? (2 * IMH - 2 - gy) : gy);
            gx = (gx < 0) ? -gx : ((gx >= IMW) ? (2 * IMW - 2 - gx) : gx);
            int g = gy * IMW + gx;
            float p0 = xb[0 * IMH * IMW + g];
            float p1 = xb[1 * IMH * IMW + g];
            float p2 = xb[2 * IMH * IMW + g];
            float p3 = xb[3 * IMH * IMW + g];
            float4 v;
            v.x = SC * (p0 + p1);
            v.y = SC * (p0 - p1);
            v.z = SC * (p2 + p3);
            v.w = SC * (p2 - p3);
            tile[py][px] = v;
        }
    }
    __syncthreads();

    // ---- 2 threads per output: lanes i and i^16 split the 13 rows 7/6 ----
    const int lane = tid & 31;
    const int wrp  = tid >> 5;            // 0..3
    const int half = lane >> 4;           // 0: rows 0..6, 1: rows 7..12
    const int o    = wrp * 16 + (lane & 15);  // 0..63
    const int lx   = o & (TW - 1);        // 0..31
    const int ly   = o >> 5;              // 0..1

    const float4 c = tile[ly + RAD][lx + RAD];

    float ws = 0.f, aU01 = 0.f, aV01 = 0.f, aU23 = 0.f, aV23 = 0.f;

    const int rbase = half * 7;
    const int nrows = 7 - half;           // 7 or 6

    #pragma unroll 1
    for (int r = 0; r < nrows; r++) {
        const int row = rbase + r;
        const float4* rp = &tile[ly + row][lx];
        const float*  T  = &s_T[row * KS];
        #pragma unroll
        for (int ix = 0; ix < KS; ix++) {
            float4 p = rp[ix];
            float m01 = fmaxf(fabsf(p.x - c.x), fabsf(p.y - c.y));
            float m23 = fmaxf(fabsf(p.z - c.z), fabsf(p.w - c.w));
            float d   = m01 + m23;
            float w   = fast_ex2(fmaf(d, -d, T[ix]));
            ws += w;
            aU01 = fmaf(w, p.x, aU01);
            aV01 = fmaf(w, p.y, aV01);
            aU23 = fmaf(w, p.z, aU23);
            aV23 = fmaf(w, p.w, aV23);
        }
    }

    // ---- combine halves (partner = lane ^ 16) ----
    ws   += __shfl_xor_sync(0xffffffffu, ws,   16);
    aU01 += __shfl_xor_sync(0xffffffffu, aU01, 16);
    aV01 += __shfl_xor_sync(0xffffffffu, aV01, 16);
    aU23 += __shfl_xor_sync(0xffffffffu, aU23, 16);
    aV23 += __shfl_xor_sync(0xffffffffu, aV23, 16);

    // ---- epilogue: each half stores 2 channels ----
    const float hinv = __fdividef(0.5f, SC * ws);
    float* ob = out + (size_t)b * NC * IMH * IMW;
    const int oo = (ty0 + ly) * IMW + (tx0 + lx);
    if (half == 0) {
        ob[0 * IMH * IMW + oo] = (aU01 + aV01) * hinv;
        ob[1 * IMH * IMW + oo] = (aU01 - aV01) * hinv;
    } else {
        ob[2 * IMH * IMW + oo] = (aU23 + aV23) * hinv;
        ob[3 * IMH * IMW + oo] = (aU23 - aV23) * hinv;
    }
}

extern "C" void kernel_launch(void* const* d_in, const int* in_sizes, int n_in,
                              void* d_out, int out_size) {
    const float* x = (const float*)d_in[0];
    float* out = (float*)d_out;
    dim3 grid(IMW / TW, IMH / TH, NB);   // 8 x 128 x 2 = 2048 blocks
    bilateral13_v7<<<grid, NT>>>(x, out);
}

// round 8
// speedup vs baseline: 1.1100x; 1.1100x over previous
#include <cuda_runtime.h>

#define KS   13
#define RAD  6
#define TW   32
#define TH   4            // 32x4 outputs per block, 1 per thread
#define PW   (TW + 2*RAD) // 44
#define PH   (TH + 2*RAD) // 16
#define IMH  256
#define IMW  256
#define NC   4
#define NB   2
#define NT   128

__device__ __forceinline__ float fast_ex2(float x) {
    float r; asm("ex2.approx.ftz.f32 %0, %1;" : "=f"(r) : "f"(x)); return r;
}

__global__ __launch_bounds__(NT, 8)
void bilateral13_v8(const float* __restrict__ x, float* __restrict__ out) {
    __shared__ float4 tile[PH][PW];   // plain (u01, v01, u23, v23) basis (no pre-scale)
    __shared__ float  s_T[KS * KS];   // K2 * ((iy-6)^2 + (ix-6)^2)

    const int tid = threadIdx.x;      // 0..127
    const int b   = blockIdx.z;
    const int tx0 = blockIdx.x * TW;
    const int ty0 = blockIdx.y * TH;

    // K2 = -0.5/9 * log2(e)  (sigma_color = sigma_space = 3; norm cancels)
    const float K2 = (-0.5f / 9.0f) * 1.4426950408889634f;
    const float SC = 0.28311592f;     // sqrt(-K2): applied inside diff as FFMA-imm

    // ---- spatial table ----
    for (int e = tid; e < KS * KS; e += NT) {
        const int iy = e / KS - RAD;
        const int ix = e % KS - RAD;
        s_T[e] = K2 * (float)(iy * iy + ix * ix);
    }

    // ---- cooperative load: reflect pad + (u,v) basis change ----------------
    const float* xb = x + (size_t)b * NC * IMH * IMW;
    #pragma unroll
    for (int it = 0; it < (PH * PW + NT - 1) / NT; it++) {
        int i = tid + it * NT;
        if (i < PH * PW) {
            int py = i / PW, px = i % PW;
            int gy = ty0 + py - RAD;
            int gx = tx0 + px - RAD;
            gy = (gy < 0) ? -gy : ((gy >= IMH) ? (2 * IMH - 2 - gy) : gy);
            gx = (gx < 0) ? -gx : ((gx >= IMW) ? (2 * IMW - 2 - gx) : gx);
            int g = gy * IMW + gx;
            float p0 = xb[0 * IMH * IMW + g];
            float p1 = xb[1 * IMH * IMW + g];
            float p2 = xb[2 * IMH * IMW + g];
            float p3 = xb[3 * IMH * IMW + g];
            float4 v;
            v.x = p0 + p1;   // u01
            v.y = p0 - p1;   // v01
            v.z = p2 + p3;   // u23
            v.w = p2 - p3;   // v23
            tile[py][px] = v;
        }
    }
    __syncthreads();

    // ---- per-thread: one output pixel ----
    const int lx = tid & (TW - 1);    // 0..31
    const int ly = tid >> 5;          // 0..3

    const float4 c = tile[ly + RAD][lx + RAD];
    // precompute -SC*c so each diff is a single FFMA with SC as IMMEDIATE (rt=1)
    const float ncx = -SC * c.x;
    const float ncy = -SC * c.y;
    const float ncz = -SC * c.z;
    const float ncw = -SC * c.w;

    float accU01 = 0.f, accV01 = 0.f, accU23 = 0.f, accV23 = 0.f;
    float ws = 0.f;                   // accumulates 2*sum(w) via FFMA-imm

    #pragma unroll 1
    for (int iy = 0; iy < KS; iy++) {
        const float4* rp = &tile[ly + iy][lx];
        const float*  T  = &s_T[iy * KS];
        #pragma unroll
        for (int ix = 0; ix < KS; ix++) {
            float4 p = rp[ix];
            // 4x FFMA-imm (rt=1): scaled diffs
            float d0 = __fmaf_rn(p.x, SC, ncx);
            float d1 = __fmaf_rn(p.y, SC, ncy);
            float d2 = __fmaf_rn(p.z, SC, ncz);
            float d3 = __fmaf_rn(p.w, SC, ncw);
            // |a|+|b| = max(|a+b|,|a-b|) in (u,v) basis -> FMNMX on ALU pipe
            float m01 = fmaxf(fabsf(d0), fabsf(d1));
            float m23 = fmaxf(fabsf(d2), fabsf(d3));
            float d   = m01 + m23;                       // = SC * L1-distance
            float w   = fast_ex2(__fmaf_rn(d, -d, T[ix]));  // T - (SC*L1)^2
            ws = __fmaf_rn(w, 2.0f, ws);                 // FFMA-imm (rt=1)
            accU01 = __fmaf_rn(w, p.x, accU01);
            accV01 = __fmaf_rn(w, p.y, accV01);
            accU23 = __fmaf_rn(w, p.z, accU23);
            accV23 = __fmaf_rn(w, p.w, accV23);
        }
    }

    // ---- epilogue: undo basis change, normalize (ws = 2*sum w) ----
    const float hinv = __fdividef(1.0f, ws);   // = 0.5 / sum(w)
    float* ob = out + (size_t)b * NC * IMH * IMW;
    const int o = (ty0 + ly) * IMW + (tx0 + lx);
    ob[0 * IMH * IMW + o] = (accU01 + accV01) * hinv;
    ob[1 * IMH * IMW + o] = (accU01 - accV01) * hinv;
    ob[2 * IMH * IMW + o] = (accU23 + accV23) * hinv;
    ob[3 * IMH * IMW + o] = (accU23 - accV23) * hinv;
}

extern "C" void kernel_launch(void* const* d_in, const int* in_sizes, int n_in,
                              void* d_out, int out_size) {
    const float* x = (const float*)d_in[0];
    float* out = (float*)d_out;
    dim3 grid(IMW / TW, IMH / TH, NB);   // 8 x 64 x 2 = 1024 blocks
    bilateral13_v8<<<grid, NT>>>(x, out);
}